// round 3
// baseline (speedup 1.0000x reference)
#include <cuda_runtime.h>

// ---------------------------------------------------------------------------
// Non-local attention block, B=8, C=512, H=W=32 (N=1024), fp32.
//   feat = [Wphi;Wtheta;Wbeta] @ X_b  (+bias)      -> g_feat (phi,theta,beta)
//   S    = phi^T @ theta                           -> g_S
//   A    = row-softmax(S)                          (in place)
//   out  = beta @ A + X
// ---------------------------------------------------------------------------

namespace {
constexpr int Cd  = 512;
constexpr int Nd  = 1024;
constexpr int Bd  = 8;
constexpr int CN  = Cd * Nd;      // 524288
constexpr int NNs = Nd * Nd;      // 1048576

constexpr int BM = 128, BN = 128, BK = 8, TM = 8, TN = 8;
}  // namespace

// Scratch (uninitialized __device__ globals: driver-allocated at load, legal).
__device__ float g_feat[3 * Bd * CN];   // 48 MB: [t][b][c][n]
__device__ float g_S[Bd * NNs];         // 32 MB: [b][n][m]

// ---------------------------------------------------------------------------
// Kernel 1: fused 1x1 convs. C[r,n] = sum_k Wstack[r,k] * X_b[k,n] + bias
// grid (Nd/BN=8, 1536/BM=12, Bd=8), block 256
// ---------------------------------------------------------------------------
__global__ __launch_bounds__(256)
void k_conv(const float* __restrict__ X,
            const float* __restrict__ W0, const float* __restrict__ bias0,
            const float* __restrict__ W1, const float* __restrict__ bias1,
            const float* __restrict__ W2, const float* __restrict__ bias2)
{
    __shared__ float As[BK][BM];
    __shared__ float Bs[BK][BN];

    const int b  = blockIdx.z;
    const int my = blockIdx.y;            // 0..11 across stacked 1536 rows
    const int n0 = blockIdx.x * BN;
    const int t  = my >> 2;               // which weight (512/128 = 4 tiles each)
    const int o0 = (my & 3) * BM;         // row offset within that weight

    const float* __restrict__ W    = (t == 0) ? W0    : (t == 1) ? W1    : W2;
    const float* __restrict__ bias = (t == 0) ? bias0 : (t == 1) ? bias1 : bias2;
    const float* __restrict__ Bm   = X + (size_t)b * CN;
    float* __restrict__ Cm = g_feat + ((size_t)t * Bd + b) * CN;

    const int tid = threadIdx.x;
    const int tx  = tid & 15, ty = tid >> 4;

    const int a_row = tid >> 1;           // 0..127
    const int a_k4  = (tid & 1) * 4;      // 0 or 4
    const int b_kr  = tid >> 5;           // 0..7
    const int b_n4  = (tid & 31) * 4;     // 0..124

    float acc[TM][TN];
    #pragma unroll
    for (int i = 0; i < TM; i++)
        #pragma unroll
        for (int j = 0; j < TN; j++) acc[i][j] = 0.f;

    for (int k0 = 0; k0 < Cd; k0 += BK) {
        float4 av = *reinterpret_cast<const float4*>(
            &W[(size_t)(o0 + a_row) * Cd + k0 + a_k4]);
        As[a_k4 + 0][a_row] = av.x;
        As[a_k4 + 1][a_row] = av.y;
        As[a_k4 + 2][a_row] = av.z;
        As[a_k4 + 3][a_row] = av.w;
        *reinterpret_cast<float4*>(&Bs[b_kr][b_n4]) =
            *reinterpret_cast<const float4*>(&Bm[(size_t)(k0 + b_kr) * Nd + n0 + b_n4]);
        __syncthreads();

        #pragma unroll
        for (int k = 0; k < BK; ++k) {
            float ra[TM], rb[TN];
            #pragma unroll
            for (int i = 0; i < TM; i++) ra[i] = As[k][ty * TM + i];
            #pragma unroll
            for (int j = 0; j < TN; j++) rb[j] = Bs[k][tx * TN + j];
            #pragma unroll
            for (int i = 0; i < TM; i++)
                #pragma unroll
                for (int j = 0; j < TN; j++) acc[i][j] += ra[i] * rb[j];
        }
        __syncthreads();
    }

    #pragma unroll
    for (int i = 0; i < TM; i++) {
        const int row = o0 + ty * TM + i;
        const float bv = bias[row];
        float* crow = Cm + (size_t)row * Nd + n0 + tx * TN;
        #pragma unroll
        for (int j = 0; j < TN; j += 4) {
            float4 v = make_float4(acc[i][j] + bv, acc[i][j + 1] + bv,
                                   acc[i][j + 2] + bv, acc[i][j + 3] + bv);
            *reinterpret_cast<float4*>(crow + j) = v;
        }
    }
}

// ---------------------------------------------------------------------------
// Kernel 2: S[n,m] = sum_c phi[c,n] * theta[c,m]  (TN gemm; both K-major)
// grid (Nd/BN=8, Nd/BM=8, Bd=8), block 256
// ---------------------------------------------------------------------------
__global__ __launch_bounds__(256)
void k_scores()
{
    __shared__ float As[BK][BM];
    __shared__ float Bs[BK][BN];

    const int b  = blockIdx.z;
    const int m0 = blockIdx.y * BM;   // output row (n of S)
    const int n0 = blockIdx.x * BN;   // output col (m of S)

    const float* __restrict__ A  = g_feat + ((size_t)0 * Bd + b) * CN;  // phi
    const float* __restrict__ Bm = g_feat + ((size_t)1 * Bd + b) * CN;  // theta
    float* __restrict__ Cm = g_S + (size_t)b * NNs;

    const int tid = threadIdx.x;
    const int tx  = tid & 15, ty = tid >> 4;
    const int kr  = tid >> 5;            // 0..7
    const int c4  = (tid & 31) * 4;      // 0..124

    float acc[TM][TN];
    #pragma unroll
    for (int i = 0; i < TM; i++)
        #pragma unroll
        for (int j = 0; j < TN; j++) acc[i][j] = 0.f;

    for (int k0 = 0; k0 < Cd; k0 += BK) {
        *reinterpret_cast<float4*>(&As[kr][c4]) =
            *reinterpret_cast<const float4*>(&A[(size_t)(k0 + kr) * Nd + m0 + c4]);
        *reinterpret_cast<float4*>(&Bs[kr][c4]) =
            *reinterpret_cast<const float4*>(&Bm[(size_t)(k0 + kr) * Nd + n0 + c4]);
        __syncthreads();

        #pragma unroll
        for (int k = 0; k < BK; ++k) {
            float ra[TM], rb[TN];
            #pragma unroll
            for (int i = 0; i < TM; i++) ra[i] = As[k][ty * TM + i];
            #pragma unroll
            for (int j = 0; j < TN; j++) rb[j] = Bs[k][tx * TN + j];
            #pragma unroll
            for (int i = 0; i < TM; i++)
                #pragma unroll
                for (int j = 0; j < TN; j++) acc[i][j] += ra[i] * rb[j];
        }
        __syncthreads();
    }

    #pragma unroll
    for (int i = 0; i < TM; i++) {
        float* crow = Cm + (size_t)(m0 + ty * TM + i) * Nd + n0 + tx * TN;
        #pragma unroll
        for (int j = 0; j < TN; j += 4) {
            *reinterpret_cast<float4*>(crow + j) =
                make_float4(acc[i][j], acc[i][j + 1], acc[i][j + 2], acc[i][j + 3]);
        }
    }
}

// ---------------------------------------------------------------------------
// Kernel 3: row softmax of g_S (8192 rows x 1024). One block per row.
// ---------------------------------------------------------------------------
__global__ __launch_bounds__(256)
void k_softmax()
{
    __shared__ float red[8];
    float* __restrict__ p = g_S + (size_t)blockIdx.x * Nd;

    const int tid = threadIdx.x;
    const int lane = tid & 31, warp = tid >> 5;

    float4 v = *reinterpret_cast<const float4*>(p + tid * 4);

    // row max
    float m = fmaxf(fmaxf(v.x, v.y), fmaxf(v.z, v.w));
    #pragma unroll
    for (int o = 16; o; o >>= 1) m = fmaxf(m, __shfl_xor_sync(0xffffffffu, m, o));
    if (lane == 0) red[warp] = m;
    __syncthreads();
    float rowmax = red[0];
    #pragma unroll
    for (int i = 1; i < 8; i++) rowmax = fmaxf(rowmax, red[i]);
    __syncthreads();

    // exp + row sum
    float4 e;
    e.x = __expf(v.x - rowmax);
    e.y = __expf(v.y - rowmax);
    e.z = __expf(v.z - rowmax);
    e.w = __expf(v.w - rowmax);
    float s = (e.x + e.y) + (e.z + e.w);
    #pragma unroll
    for (int o = 16; o; o >>= 1) s += __shfl_xor_sync(0xffffffffu, s, o);
    if (lane == 0) red[warp] = s;
    __syncthreads();
    float rowsum = red[0];
    #pragma unroll
    for (int i = 1; i < 8; i++) rowsum += red[i];

    const float inv = 1.0f / rowsum;
    e.x *= inv; e.y *= inv; e.z *= inv; e.w *= inv;
    *reinterpret_cast<float4*>(p + tid * 4) = e;
}

// ---------------------------------------------------------------------------
// Kernel 4: out[c,m] = sum_n beta[c,n] * A[n,m] + X[c,m]
// grid (Nd/BN=8, Cd/BM=4, Bd=8), block 256
// ---------------------------------------------------------------------------
__global__ __launch_bounds__(256)
void k_out(const float* __restrict__ X, float* __restrict__ out)
{
    __shared__ float As[BK][BM];
    __shared__ float Bs[BK][BN];

    const int b  = blockIdx.z;
    const int c0 = blockIdx.y * BM;
    const int n0 = blockIdx.x * BN;

    const float* __restrict__ A  = g_feat + ((size_t)2 * Bd + b) * CN;  // beta [C][N]
    const float* __restrict__ Bm = g_S + (size_t)b * NNs;               // A [N][M]

    const int tid = threadIdx.x;
    const int tx  = tid & 15, ty = tid >> 4;

    const int a_row = tid >> 1;
    const int a_k4  = (tid & 1) * 4;
    const int b_kr  = tid >> 5;
    const int b_n4  = (tid & 31) * 4;

    float acc[TM][TN];
    #pragma unroll
    for (int i = 0; i < TM; i++)
        #pragma unroll
        for (int j = 0; j < TN; j++) acc[i][j] = 0.f;

    for (int k0 = 0; k0 < Nd; k0 += BK) {
        float4 av = *reinterpret_cast<const float4*>(
            &A[(size_t)(c0 + a_row) * Nd + k0 + a_k4]);
        As[a_k4 + 0][a_row] = av.x;
        As[a_k4 + 1][a_row] = av.y;
        As[a_k4 + 2][a_row] = av.z;
        As[a_k4 + 3][a_row] = av.w;
        *reinterpret_cast<float4*>(&Bs[b_kr][b_n4]) =
            *reinterpret_cast<const float4*>(&Bm[(size_t)(k0 + b_kr) * Nd + n0 + b_n4]);
        __syncthreads();

        #pragma unroll
        for (int k = 0; k < BK; ++k) {
            float ra[TM], rb[TN];
            #pragma unroll
            for (int i = 0; i < TM; i++) ra[i] = As[k][ty * TM + i];
            #pragma unroll
            for (int j = 0; j < TN; j++) rb[j] = Bs[k][tx * TN + j];
            #pragma unroll
            for (int i = 0; i < TM; i++)
                #pragma unroll
                for (int j = 0; j < TN; j++) acc[i][j] += ra[i] * rb[j];
        }
        __syncthreads();
    }

    #pragma unroll
    for (int i = 0; i < TM; i++) {
        const size_t base = (size_t)b * CN + (size_t)(c0 + ty * TM + i) * Nd + n0 + tx * TN;
        #pragma unroll
        for (int j = 0; j < TN; j += 4) {
            float4 xv = *reinterpret_cast<const float4*>(X + base + j);
            float4 v  = make_float4(acc[i][j] + xv.x, acc[i][j + 1] + xv.y,
                                    acc[i][j + 2] + xv.z, acc[i][j + 3] + xv.w);
            *reinterpret_cast<float4*>(out + base + j) = v;
        }
    }
}

// ---------------------------------------------------------------------------
extern "C" void kernel_launch(void* const* d_in, const int* in_sizes, int n_in,
                              void* d_out, int out_size)
{
    (void)in_sizes; (void)n_in; (void)out_size;
    const float* X  = (const float*)d_in[0];
    const float* Wp = (const float*)d_in[1];
    const float* bp = (const float*)d_in[2];
    const float* Wt = (const float*)d_in[3];
    const float* bt = (const float*)d_in[4];
    const float* Wb = (const float*)d_in[5];
    const float* bb = (const float*)d_in[6];
    float* out = (float*)d_out;

    k_conv   <<<dim3(Nd / BN, (3 * Cd) / BM, Bd), 256>>>(X, Wp, bp, Wt, bt, Wb, bb);
    k_scores <<<dim3(Nd / BN, Nd / BM, Bd), 256>>>();
    k_softmax<<<Bd * Nd, 256>>>();
    k_out    <<<dim3(Nd / BN, Cd / BM, Bd), 256>>>(X, out);
}

// round 4
// speedup vs baseline: 1.0557x; 1.0557x over previous
#include <cuda_runtime.h>

// ---------------------------------------------------------------------------
// Non-local attention block, B=8, C=512, H=W=32 (N=1024), fp32.
// R3: packed fma.rn.f32x2 inner product (2x fp32 MAC rate on sm_100a),
//     BK=16, double-buffered smem, one __syncthreads per k-tile.
// ---------------------------------------------------------------------------

namespace {
constexpr int Cd  = 512;
constexpr int Nd  = 1024;
constexpr int Bd  = 8;
constexpr int CN  = Cd * Nd;      // 524288
constexpr int NNs = Nd * Nd;      // 1048576

constexpr int BM = 128, BN = 128, BK = 16;
}  // namespace

// Scratch (uninitialized __device__ globals: driver-allocated at load, legal).
__device__ float g_feat[3 * Bd * CN];   // 48 MB: [t][b][c][n]
__device__ float g_S[Bd * NNs];         // 32 MB: [b][n][m]

// ---- packed f32x2 helpers -------------------------------------------------
__device__ __forceinline__ unsigned long long pk2(float lo, float hi) {
    unsigned long long r;
    asm("mov.b64 %0, {%1, %2};" : "=l"(r) : "f"(lo), "f"(hi));
    return r;
}
__device__ __forceinline__ void upk2(float& lo, float& hi, unsigned long long v) {
    asm("mov.b64 {%0, %1}, %2;" : "=f"(lo), "=f"(hi) : "l"(v));
}
__device__ __forceinline__ void ffma2(unsigned long long& d,
                                      unsigned long long a, unsigned long long b) {
    asm("fma.rn.f32x2 %0, %1, %2, %0;" : "+l"(d) : "l"(a), "l"(b));
}

// Compute 16 k-steps on the given smem buffers into packed accumulators.
// acc[i][j] holds output columns (2j, 2j+1) for micro-row i.
__device__ __forceinline__ void mma_tile(const float (*__restrict__ As)[BM],
                                         const float (*__restrict__ Bs)[BN],
                                         int ty, int tx,
                                         unsigned long long (&acc)[8][4]) {
    #pragma unroll
    for (int k = 0; k < BK; ++k) {
        const float* as = &As[k][ty * 8];
        const float* bs = &Bs[k][tx * 8];
        float4 a0 = *reinterpret_cast<const float4*>(as);
        float4 a1 = *reinterpret_cast<const float4*>(as + 4);
        float4 b0 = *reinterpret_cast<const float4*>(bs);
        float4 b1 = *reinterpret_cast<const float4*>(bs + 4);
        unsigned long long rb[4] = {pk2(b0.x, b0.y), pk2(b0.z, b0.w),
                                    pk2(b1.x, b1.y), pk2(b1.z, b1.w)};
        float av[8] = {a0.x, a0.y, a0.z, a0.w, a1.x, a1.y, a1.z, a1.w};
        #pragma unroll
        for (int i = 0; i < 8; ++i) {
            unsigned long long ai = pk2(av[i], av[i]);
            #pragma unroll
            for (int j = 0; j < 4; ++j) ffma2(acc[i][j], ai, rb[j]);
        }
    }
}

// ---------------------------------------------------------------------------
// Kernel 1: fused 1x1 convs. C[r,n] = sum_k Wstack[r,k] * X_b[k,n] + bias
// grid (Nd/BN=8, 1536/BM=12, Bd=8), block 256. A is row-major (transpose-store).
// ---------------------------------------------------------------------------
__global__ __launch_bounds__(256, 2)
void k_conv(const float* __restrict__ X,
            const float* __restrict__ W0, const float* __restrict__ bias0,
            const float* __restrict__ W1, const float* __restrict__ bias1,
            const float* __restrict__ W2, const float* __restrict__ bias2)
{
    __shared__ float As[2][BK][BM];
    __shared__ float Bs[2][BK][BN];

    const int b  = blockIdx.z;
    const int my = blockIdx.y;
    const int n0 = blockIdx.x * BN;
    const int t  = my >> 2;
    const int o0 = (my & 3) * BM;

    const float* __restrict__ W    = (t == 0) ? W0    : (t == 1) ? W1    : W2;
    const float* __restrict__ bias = (t == 0) ? bias0 : (t == 1) ? bias1 : bias2;
    const float* __restrict__ Bm   = X + (size_t)b * CN;
    float* __restrict__ Cm = g_feat + ((size_t)t * Bd + b) * CN;

    const int tid = threadIdx.x;
    const int tx  = tid & 15, ty = tid >> 4;

    // A loader (transpose): row = tid&127, kb = (tid>>7)*8
    const int a_row = tid & 127;
    const int a_kb  = (tid >> 7) * 8;
    // B loader (direct): k = tid>>4, m8 = (tid&15)*8
    const int b_k  = tid >> 4;
    const int b_m8 = (tid & 15) * 8;

    unsigned long long acc[8][4];
    #pragma unroll
    for (int i = 0; i < 8; i++)
        #pragma unroll
        for (int j = 0; j < 4; j++) acc[i][j] = 0ull;

    float4 pa0, pa1, pb0, pb1;
    const float* aptr = &W[(size_t)(o0 + a_row) * Cd];

    // prologue: tile 0
    pa0 = *reinterpret_cast<const float4*>(aptr + a_kb);
    pa1 = *reinterpret_cast<const float4*>(aptr + a_kb + 4);
    pb0 = *reinterpret_cast<const float4*>(&Bm[(size_t)b_k * Nd + n0 + b_m8]);
    pb1 = *reinterpret_cast<const float4*>(&Bm[(size_t)b_k * Nd + n0 + b_m8 + 4]);
    {
        float av[8] = {pa0.x, pa0.y, pa0.z, pa0.w, pa1.x, pa1.y, pa1.z, pa1.w};
        #pragma unroll
        for (int i = 0; i < 8; i++) As[0][a_kb + i][a_row] = av[i];
        *reinterpret_cast<float4*>(&Bs[0][b_k][b_m8])     = pb0;
        *reinterpret_cast<float4*>(&Bs[0][b_k][b_m8 + 4]) = pb1;
    }

    const int NT = Cd / BK;  // 32
    int buf = 0;
    for (int tI = 0; tI < NT; ++tI) {
        __syncthreads();
        if (tI + 1 < NT) {
            const int k0 = (tI + 1) * BK;
            pa0 = *reinterpret_cast<const float4*>(aptr + k0 + a_kb);
            pa1 = *reinterpret_cast<const float4*>(aptr + k0 + a_kb + 4);
            pb0 = *reinterpret_cast<const float4*>(&Bm[(size_t)(k0 + b_k) * Nd + n0 + b_m8]);
            pb1 = *reinterpret_cast<const float4*>(&Bm[(size_t)(k0 + b_k) * Nd + n0 + b_m8 + 4]);
        }
        mma_tile(As[buf], Bs[buf], ty, tx, acc);
        if (tI + 1 < NT) {
            float av[8] = {pa0.x, pa0.y, pa0.z, pa0.w, pa1.x, pa1.y, pa1.z, pa1.w};
            #pragma unroll
            for (int i = 0; i < 8; i++) As[buf ^ 1][a_kb + i][a_row] = av[i];
            *reinterpret_cast<float4*>(&Bs[buf ^ 1][b_k][b_m8])     = pb0;
            *reinterpret_cast<float4*>(&Bs[buf ^ 1][b_k][b_m8 + 4]) = pb1;
        }
        buf ^= 1;
    }

    #pragma unroll
    for (int i = 0; i < 8; i++) {
        const int row = o0 + ty * 8 + i;
        const float bv = bias[row];
        float c[8];
        #pragma unroll
        for (int j = 0; j < 4; j++) upk2(c[2 * j], c[2 * j + 1], acc[i][j]);
        float* crow = Cm + (size_t)row * Nd + n0 + tx * 8;
        *reinterpret_cast<float4*>(crow) =
            make_float4(c[0] + bv, c[1] + bv, c[2] + bv, c[3] + bv);
        *reinterpret_cast<float4*>(crow + 4) =
            make_float4(c[4] + bv, c[5] + bv, c[6] + bv, c[7] + bv);
    }
}

// ---------------------------------------------------------------------------
// Kernel 2: S[n,m] = sum_c phi[c,n] * theta[c,m]  (both operands K-major)
// grid (Nd/BN=8, Nd/BM=8, Bd=8), block 256
// ---------------------------------------------------------------------------
__global__ __launch_bounds__(256, 2)
void k_scores()
{
    __shared__ float As[2][BK][BM];
    __shared__ float Bs[2][BK][BN];

    const int b  = blockIdx.z;
    const int m0 = blockIdx.y * BM;
    const int n0 = blockIdx.x * BN;

    const float* __restrict__ A  = g_feat + ((size_t)0 * Bd + b) * CN;  // phi
    const float* __restrict__ Bm = g_feat + ((size_t)1 * Bd + b) * CN;  // theta
    float* __restrict__ Cm = g_S + (size_t)b * NNs;

    const int tid = threadIdx.x;
    const int tx  = tid & 15, ty = tid >> 4;
    const int l_k  = tid >> 4;        // 0..15
    const int l_m8 = (tid & 15) * 8;  // 0..120

    unsigned long long acc[8][4];
    #pragma unroll
    for (int i = 0; i < 8; i++)
        #pragma unroll
        for (int j = 0; j < 4; j++) acc[i][j] = 0ull;

    float4 pa0, pa1, pb0, pb1;
    pa0 = *reinterpret_cast<const float4*>(&A[(size_t)l_k * Nd + m0 + l_m8]);
    pa1 = *reinterpret_cast<const float4*>(&A[(size_t)l_k * Nd + m0 + l_m8 + 4]);
    pb0 = *reinterpret_cast<const float4*>(&Bm[(size_t)l_k * Nd + n0 + l_m8]);
    pb1 = *reinterpret_cast<const float4*>(&Bm[(size_t)l_k * Nd + n0 + l_m8 + 4]);
    *reinterpret_cast<float4*>(&As[0][l_k][l_m8])     = pa0;
    *reinterpret_cast<float4*>(&As[0][l_k][l_m8 + 4]) = pa1;
    *reinterpret_cast<float4*>(&Bs[0][l_k][l_m8])     = pb0;
    *reinterpret_cast<float4*>(&Bs[0][l_k][l_m8 + 4]) = pb1;

    const int NT = Cd / BK;  // 32
    int buf = 0;
    for (int tI = 0; tI < NT; ++tI) {
        __syncthreads();
        if (tI + 1 < NT) {
            const int k0 = (tI + 1) * BK;
            pa0 = *reinterpret_cast<const float4*>(&A[(size_t)(k0 + l_k) * Nd + m0 + l_m8]);
            pa1 = *reinterpret_cast<const float4*>(&A[(size_t)(k0 + l_k) * Nd + m0 + l_m8 + 4]);
            pb0 = *reinterpret_cast<const float4*>(&Bm[(size_t)(k0 + l_k) * Nd + n0 + l_m8]);
            pb1 = *reinterpret_cast<const float4*>(&Bm[(size_t)(k0 + l_k) * Nd + n0 + l_m8 + 4]);
        }
        mma_tile(As[buf], Bs[buf], ty, tx, acc);
        if (tI + 1 < NT) {
            *reinterpret_cast<float4*>(&As[buf ^ 1][l_k][l_m8])     = pa0;
            *reinterpret_cast<float4*>(&As[buf ^ 1][l_k][l_m8 + 4]) = pa1;
            *reinterpret_cast<float4*>(&Bs[buf ^ 1][l_k][l_m8])     = pb0;
            *reinterpret_cast<float4*>(&Bs[buf ^ 1][l_k][l_m8 + 4]) = pb1;
        }
        buf ^= 1;
    }

    #pragma unroll
    for (int i = 0; i < 8; i++) {
        float c[8];
        #pragma unroll
        for (int j = 0; j < 4; j++) upk2(c[2 * j], c[2 * j + 1], acc[i][j]);
        float* crow = Cm + (size_t)(m0 + ty * 8 + i) * Nd + n0 + tx * 8;
        *reinterpret_cast<float4*>(crow)     = make_float4(c[0], c[1], c[2], c[3]);
        *reinterpret_cast<float4*>(crow + 4) = make_float4(c[4], c[5], c[6], c[7]);
    }
}

// ---------------------------------------------------------------------------
// Kernel 3: row softmax of g_S (8192 rows x 1024). One block per row.
// ---------------------------------------------------------------------------
__global__ __launch_bounds__(256)
void k_softmax()
{
    __shared__ float red[8];
    float* __restrict__ p = g_S + (size_t)blockIdx.x * Nd;

    const int tid = threadIdx.x;
    const int lane = tid & 31, warp = tid >> 5;

    float4 v = *reinterpret_cast<const float4*>(p + tid * 4);

    float m = fmaxf(fmaxf(v.x, v.y), fmaxf(v.z, v.w));
    #pragma unroll
    for (int o = 16; o; o >>= 1) m = fmaxf(m, __shfl_xor_sync(0xffffffffu, m, o));
    if (lane == 0) red[warp] = m;
    __syncthreads();
    float rowmax = red[0];
    #pragma unroll
    for (int i = 1; i < 8; i++) rowmax = fmaxf(rowmax, red[i]);
    __syncthreads();

    float4 e;
    e.x = __expf(v.x - rowmax);
    e.y = __expf(v.y - rowmax);
    e.z = __expf(v.z - rowmax);
    e.w = __expf(v.w - rowmax);
    float s = (e.x + e.y) + (e.z + e.w);
    #pragma unroll
    for (int o = 16; o; o >>= 1) s += __shfl_xor_sync(0xffffffffu, s, o);
    if (lane == 0) red[warp] = s;
    __syncthreads();
    float rowsum = red[0];
    #pragma unroll
    for (int i = 1; i < 8; i++) rowsum += red[i];

    const float inv = 1.0f / rowsum;
    e.x *= inv; e.y *= inv; e.z *= inv; e.w *= inv;
    *reinterpret_cast<float4*>(p + tid * 4) = e;
}

// ---------------------------------------------------------------------------
// Kernel 4: out[c,m] = sum_n beta[c,n] * A[n,m] + X[c,m]
// grid (Nd/BN=8, Cd/BM=4, Bd=8), block 256. A (=beta) is row-major.
// ---------------------------------------------------------------------------
__global__ __launch_bounds__(256, 2)
void k_out(const float* __restrict__ X, float* __restrict__ out)
{
    __shared__ float As[2][BK][BM];
    __shared__ float Bs[2][BK][BN];

    const int b  = blockIdx.z;
    const int c0 = blockIdx.y * BM;
    const int n0 = blockIdx.x * BN;

    const float* __restrict__ A  = g_feat + ((size_t)2 * Bd + b) * CN;  // beta [C][N]
    const float* __restrict__ Bm = g_S + (size_t)b * NNs;               // A [N][M]

    const int tid = threadIdx.x;
    const int tx  = tid & 15, ty = tid >> 4;

    const int a_row = tid & 127;
    const int a_kb  = (tid >> 7) * 8;
    const int b_k   = tid >> 4;
    const int b_m8  = (tid & 15) * 8;

    unsigned long long acc[8][4];
    #pragma unroll
    for (int i = 0; i < 8; i++)
        #pragma unroll
        for (int j = 0; j < 4; j++) acc[i][j] = 0ull;

    float4 pa0, pa1, pb0, pb1;
    const float* aptr = &A[(size_t)(c0 + a_row) * Nd];

    pa0 = *reinterpret_cast<const float4*>(aptr + a_kb);
    pa1 = *reinterpret_cast<const float4*>(aptr + a_kb + 4);
    pb0 = *reinterpret_cast<const float4*>(&Bm[(size_t)b_k * Nd + n0 + b_m8]);
    pb1 = *reinterpret_cast<const float4*>(&Bm[(size_t)b_k * Nd + n0 + b_m8 + 4]);
    {
        float av[8] = {pa0.x, pa0.y, pa0.z, pa0.w, pa1.x, pa1.y, pa1.z, pa1.w};
        #pragma unroll
        for (int i = 0; i < 8; i++) As[0][a_kb + i][a_row] = av[i];
        *reinterpret_cast<float4*>(&Bs[0][b_k][b_m8])     = pb0;
        *reinterpret_cast<float4*>(&Bs[0][b_k][b_m8 + 4]) = pb1;
    }

    const int NT = Nd / BK;  // 64
    int buf = 0;
    for (int tI = 0; tI < NT; ++tI) {
        __syncthreads();
        if (tI + 1 < NT) {
            const int k0 = (tI + 1) * BK;
            pa0 = *reinterpret_cast<const float4*>(aptr + k0 + a_kb);
            pa1 = *reinterpret_cast<const float4*>(aptr + k0 + a_kb + 4);
            pb0 = *reinterpret_cast<const float4*>(&Bm[(size_t)(k0 + b_k) * Nd + n0 + b_m8]);
            pb1 = *reinterpret_cast<const float4*>(&Bm[(size_t)(k0 + b_k) * Nd + n0 + b_m8 + 4]);
        }
        mma_tile(As[buf], Bs[buf], ty, tx, acc);
        if (tI + 1 < NT) {
            float av[8] = {pa0.x, pa0.y, pa0.z, pa0.w, pa1.x, pa1.y, pa1.z, pa1.w};
            #pragma unroll
            for (int i = 0; i < 8; i++) As[buf ^ 1][a_kb + i][a_row] = av[i];
            *reinterpret_cast<float4*>(&Bs[buf ^ 1][b_k][b_m8])     = pb0;
            *reinterpret_cast<float4*>(&Bs[buf ^ 1][b_k][b_m8 + 4]) = pb1;
        }
        buf ^= 1;
    }

    #pragma unroll
    for (int i = 0; i < 8; i++) {
        const size_t base = (size_t)b * CN + (size_t)(c0 + ty * 8 + i) * Nd + n0 + tx * 8;
        float c[8];
        #pragma unroll
        for (int j = 0; j < 4; j++) upk2(c[2 * j], c[2 * j + 1], acc[i][j]);
        float4 x0 = *reinterpret_cast<const float4*>(X + base);
        float4 x1 = *reinterpret_cast<const float4*>(X + base + 4);
        *reinterpret_cast<float4*>(out + base) =
            make_float4(c[0] + x0.x, c[1] + x0.y, c[2] + x0.z, c[3] + x0.w);
        *reinterpret_cast<float4*>(out + base + 4) =
            make_float4(c[4] + x1.x, c[5] + x1.y, c[6] + x1.z, c[7] + x1.w);
    }
}

// ---------------------------------------------------------------------------
extern "C" void kernel_launch(void* const* d_in, const int* in_sizes, int n_in,
                              void* d_out, int out_size)
{
    (void)in_sizes; (void)n_in; (void)out_size;
    const float* X  = (const float*)d_in[0];
    const float* Wp = (const float*)d_in[1];
    const float* bp = (const float*)d_in[2];
    const float* Wt = (const float*)d_in[3];
    const float* bt = (const float*)d_in[4];
    const float* Wb = (const float*)d_in[5];
    const float* bb = (const float*)d_in[6];
    float* out = (float*)d_out;

    k_conv   <<<dim3(Nd / BN, (3 * Cd) / BM, Bd), 256>>>(X, Wp, bp, Wt, bt, Wb, bb);
    k_scores <<<dim3(Nd / BN, Nd / BM, Bd), 256>>>();
    k_softmax<<<Bd * Nd, 256>>>();
    k_out    <<<dim3(Nd / BN, Cd / BM, Bd), 256>>>(X, out);
}

// round 6
// speedup vs baseline: 1.6564x; 1.5689x over previous
#include <cuda_runtime.h>
#include <cuda_bf16.h>
#include <cstdint>

// ---------------------------------------------------------------------------
// Non-local attention block, B=8, C=512, N=1024 (H=W=32), fp32 in/out.
// R5: all four GEMMs on tensor cores via mma.sync.m16n8k16 (bf16 x3-pass
//     split emulating fp32). tcgen05 unavailable (harness targets compute_100).
//   prep:   XT hi/lo = split(transpose(X));  Wsp hi/lo = split([Wphi;Wth;Wb])
//   conv1:  featT[n][r] = XT . Wsp(phi,theta) + bias   (bf16 split out)
//   conv2:  beta[c][n]  = Wsp(beta) . XT + bias        (bf16 split out)
//   scores: S[n][m] = phiT . thetaT                    (fp32 out)
//   softmax rows of S (fp32, in place)
//   trS:    AT hi/lo = split(transpose(S))
//   z:      out[c][m] = beta . AT + X                  (fp32 out)
// ---------------------------------------------------------------------------

namespace {
constexpr int Cd = 512, Nd = 1024, Bd = 8;
constexpr int ROWB   = 80;                 // padded smem row (32 bf16 = 64B data)
constexpr int TILE_B = 128 * ROWB;         // 10240 B per operand-half tile
constexpr int BUF_B  = 4 * TILE_B;         // Ahi,Alo,Bhi,Blo = 40960
constexpr int SM_TOTAL = 2 * BUF_B;        // 81920 (double buffer)
}

// ---- device scratch (static device globals; no runtime allocation) --------
__device__ __nv_bfloat16 g_XT_hi[Bd * Nd * Cd];
__device__ __nv_bfloat16 g_XT_lo[Bd * Nd * Cd];
__device__ __nv_bfloat16 g_Wsp_hi[3 * Cd * Cd];   // rows: phi 0-511, theta 512-1023, beta 1024-1535
__device__ __nv_bfloat16 g_Wsp_lo[3 * Cd * Cd];
__device__ float         g_bias[3 * Cd];
__device__ __nv_bfloat16 g_featT_hi[Bd * Nd * Nd]; // [b][n][r], r: phi 0-511, theta 512-1023
__device__ __nv_bfloat16 g_featT_lo[Bd * Nd * Nd];
__device__ __nv_bfloat16 g_beta_hi[Bd * Cd * Nd];  // [b][c][n]
__device__ __nv_bfloat16 g_beta_lo[Bd * Cd * Nd];
__device__ float         g_S[Bd * Nd * Nd];        // [b][n][m]
__device__ __nv_bfloat16 g_AT_hi[Bd * Nd * Nd];    // [b][m][n]
__device__ __nv_bfloat16 g_AT_lo[Bd * Nd * Nd];

// ---- helpers ---------------------------------------------------------------
__device__ __forceinline__ uint32_t smem_u32(const void* p) {
    uint32_t a;
    asm("{ .reg .u64 t; cvta.to.shared.u64 t, %1; cvt.u32.u64 %0, t; }"
        : "=r"(a) : "l"(p));
    return a;
}
__device__ __forceinline__ void ldm_x4(uint32_t (&r)[4], uint32_t addr) {
    asm volatile("ldmatrix.sync.aligned.m8n8.x4.shared.b16 {%0,%1,%2,%3}, [%4];"
        : "=r"(r[0]), "=r"(r[1]), "=r"(r[2]), "=r"(r[3]) : "r"(addr));
}
__device__ __forceinline__ void mma_bf16(float (&d)[4], const uint32_t (&a)[4],
                                         const uint32_t b0, const uint32_t b1) {
    asm volatile(
        "mma.sync.aligned.m16n8k16.row.col.f32.bf16.bf16.f32 "
        "{%0,%1,%2,%3},{%4,%5,%6,%7},{%8,%9},{%0,%1,%2,%3};"
        : "+f"(d[0]), "+f"(d[1]), "+f"(d[2]), "+f"(d[3])
        : "r"(a[0]), "r"(a[1]), "r"(a[2]), "r"(a[3]), "r"(b0), "r"(b1));
}
__device__ __forceinline__ void split_bf16(float v, __nv_bfloat16& h, __nv_bfloat16& l) {
    h = __float2bfloat16(v);
    l = __float2bfloat16(v - __bfloat162float(h));
}

// ---------------------------------------------------------------------------
// prep W: split the three weight matrices into stacked bf16 hi/lo + bias vector
// ---------------------------------------------------------------------------
__global__ __launch_bounds__(256)
void k_prep_w(const float* __restrict__ Wp, const float* __restrict__ bp,
              const float* __restrict__ Wt, const float* __restrict__ bt,
              const float* __restrict__ Wb, const float* __restrict__ bb)
{
    int i = blockIdx.x * 256 + threadIdx.x;   // < 1536*512
    int r = i >> 9, c = i & 511;
    const float* W = (r < 512) ? Wp : (r < 1024) ? Wt : Wb;
    float v = W[(size_t)(r & 511) * Cd + c];
    split_bf16(v, g_Wsp_hi[i], g_Wsp_lo[i]);
    if (i < 3 * Cd)
        g_bias[i] = (i < 512) ? bp[i] : (i < 1024) ? bt[i - 512] : bb[i - 1024];
}

// ---------------------------------------------------------------------------
// prep X: transpose + split: XT[b][n][c] = X[b][c][n]
// ---------------------------------------------------------------------------
__global__ __launch_bounds__(256)
void k_prep_x(const float* __restrict__ X)
{
    __shared__ float t[32][33];
    const int b = blockIdx.z, n0 = blockIdx.x * 32, c0 = blockIdx.y * 32;
    const int tx = threadIdx.x, ty = threadIdx.y;
    #pragma unroll
    for (int r = 0; r < 4; r++)
        t[ty + 8 * r][tx] = X[((size_t)b * Cd + c0 + ty + 8 * r) * Nd + n0 + tx];
    __syncthreads();
    #pragma unroll
    for (int r = 0; r < 4; r++) {
        float v = t[tx][ty + 8 * r];
        size_t o = ((size_t)b * Nd + n0 + ty + 8 * r) * Cd + c0 + tx;
        split_bf16(v, g_XT_hi[o], g_XT_lo[o]);
    }
}

// ---------------------------------------------------------------------------
// transpose + split post-softmax attention: AT[b][m][n] = S[b][n][m]
// ---------------------------------------------------------------------------
__global__ __launch_bounds__(256)
void k_trS()
{
    __shared__ float t[32][33];
    const int b = blockIdx.z, m0 = blockIdx.x * 32, n0 = blockIdx.y * 32;
    const int tx = threadIdx.x, ty = threadIdx.y;
    #pragma unroll
    for (int r = 0; r < 4; r++)
        t[ty + 8 * r][tx] = g_S[((size_t)b * Nd + n0 + ty + 8 * r) * Nd + m0 + tx];
    __syncthreads();
    #pragma unroll
    for (int r = 0; r < 4; r++) {
        float v = t[tx][ty + 8 * r];
        size_t o = ((size_t)b * Nd + m0 + ty + 8 * r) * Nd + n0 + tx;
        split_bf16(v, g_AT_hi[o], g_AT_lo[o]);
    }
}

// ---------------------------------------------------------------------------
// row softmax of g_S (8192 rows x 1024), fp32 in place
// ---------------------------------------------------------------------------
__global__ __launch_bounds__(256)
void k_softmax()
{
    __shared__ float red[8];
    float* __restrict__ p = g_S + (size_t)blockIdx.x * Nd;
    const int tid = threadIdx.x, lane = tid & 31, warp = tid >> 5;

    float4 v = *reinterpret_cast<const float4*>(p + tid * 4);
    float m = fmaxf(fmaxf(v.x, v.y), fmaxf(v.z, v.w));
    #pragma unroll
    for (int o = 16; o; o >>= 1) m = fmaxf(m, __shfl_xor_sync(0xffffffffu, m, o));
    if (lane == 0) red[warp] = m;
    __syncthreads();
    float rowmax = red[0];
    #pragma unroll
    for (int i = 1; i < 8; i++) rowmax = fmaxf(rowmax, red[i]);
    __syncthreads();

    float4 e;
    e.x = __expf(v.x - rowmax); e.y = __expf(v.y - rowmax);
    e.z = __expf(v.z - rowmax); e.w = __expf(v.w - rowmax);
    float s = (e.x + e.y) + (e.z + e.w);
    #pragma unroll
    for (int o = 16; o; o >>= 1) s += __shfl_xor_sync(0xffffffffu, s, o);
    if (lane == 0) red[warp] = s;
    __syncthreads();
    float rowsum = red[0];
    #pragma unroll
    for (int i = 1; i < 8; i++) rowsum += red[i];

    const float inv = 1.0f / rowsum;
    e.x *= inv; e.y *= inv; e.z *= inv; e.w *= inv;
    *reinterpret_cast<float4*>(p + tid * 4) = e;
}

// ---------------------------------------------------------------------------
// mma.sync GEMM: D[128x128] fp32 = sum_k (Ahi+Alo)[row][k] (Bhi+Blo)[col][k],
// 3 passes (hh, hl, lh). Both operands K-major. 8 warps, warp tile 64x32.
// MODE 0: conv1  D[n][r] = XT . Wsp(0:1024)      K=512  -> featT bf16 split (+bias[col])
// MODE 1: conv2  D[c][n] = Wsp(beta) . XT        K=512  -> beta  bf16 split (+bias[row])
// MODE 2: scores D[n][m] = phiT . thetaT         K=512  -> g_S fp32
// MODE 3: z      D[c][m] = beta . AT  (+X)       K=1024 -> out fp32
// ---------------------------------------------------------------------------
template <int MODE>
__global__ __launch_bounds__(256, 1)
void k_gemm(const float* __restrict__ Xres, float* __restrict__ Out)
{
    extern __shared__ __align__(128) char smem[];
    const uint32_t sbase = smem_u32(smem);
    const int tid = threadIdx.x;
    const int lane = tid & 31, wid = tid >> 5;
    const int wr = wid >> 2, wc = wid & 3;          // 2x4 warp grid
    const int bz = blockIdx.z;
    const int m0 = blockIdx.y * 128, n0 = blockIdx.x * 128;

    const __nv_bfloat16 *Ah, *Al, *Bh, *Bl;
    int ldA, ldB;
    constexpr int K = (MODE == 3) ? Nd : Cd;
    if (MODE == 0) {
        Ah = g_XT_hi + (size_t)bz * Nd * Cd;  Al = g_XT_lo + (size_t)bz * Nd * Cd;
        Bh = g_Wsp_hi;                        Bl = g_Wsp_lo;
        ldA = Cd; ldB = Cd;
    } else if (MODE == 1) {
        Ah = g_Wsp_hi + (size_t)1024 * Cd;    Al = g_Wsp_lo + (size_t)1024 * Cd;
        Bh = g_XT_hi + (size_t)bz * Nd * Cd;  Bl = g_XT_lo + (size_t)bz * Nd * Cd;
        ldA = Cd; ldB = Cd;
    } else if (MODE == 2) {
        Ah = g_featT_hi + (size_t)bz * Nd * Nd;        Al = g_featT_lo + (size_t)bz * Nd * Nd;
        Bh = g_featT_hi + (size_t)bz * Nd * Nd + 512;  Bl = g_featT_lo + (size_t)bz * Nd * Nd + 512;
        ldA = Nd; ldB = Nd;
    } else {
        Ah = g_beta_hi + (size_t)bz * Cd * Nd;  Al = g_beta_lo + (size_t)bz * Cd * Nd;
        Bh = g_AT_hi + (size_t)bz * Nd * Nd;    Bl = g_AT_lo + (size_t)bz * Nd * Nd;
        ldA = Nd; ldB = Nd;
    }

    // loader role: quarter oh -> one operand-half; rows lt and lt+64, 4 chunks
    const int oh = tid >> 6, lt = tid & 63;
    const __nv_bfloat16* src;
    int row0, ld;
    if      (oh == 0) { src = Ah; row0 = m0; ld = ldA; }
    else if (oh == 1) { src = Al; row0 = m0; ld = ldA; }
    else if (oh == 2) { src = Bh; row0 = n0; ld = ldB; }
    else              { src = Bl; row0 = n0; ld = ldB; }

    float acc[4][4][4];
    #pragma unroll
    for (int i = 0; i < 4; i++)
        #pragma unroll
        for (int j = 0; j < 4; j++)
            #pragma unroll
            for (int q = 0; q < 4; q++) acc[i][j][q] = 0.f;

    // prologue: stage tile 0
    uint4 v[8];
    #pragma unroll
    for (int i = 0; i < 8; i++) {
        const int row = lt + (i >> 2) * 64, c = i & 3;
        v[i] = *reinterpret_cast<const uint4*>(src + (size_t)(row0 + row) * ld + c * 8);
    }
    {
        char* sb = smem + oh * TILE_B;
        #pragma unroll
        for (int i = 0; i < 8; i++) {
            const int row = lt + (i >> 2) * 64, c = i & 3;
            *reinterpret_cast<uint4*>(sb + row * ROWB + c * 16) = v[i];
        }
    }

    // ldmatrix lane address components
    const int a_r = lane & 15, a_c = lane >> 4;              // A: rows 0-15, chunk half
    const int b_r = (lane & 7) + ((lane & 16) >> 1);         // B: n within 16
    const int b_c = (lane >> 3) & 1;                         // B: chunk half

    constexpr int NT = K / 32;
    int buf = 0;
    for (int t = 0; t < NT; t++) {
        __syncthreads();
        if (t + 1 < NT) {
            const int k0 = (t + 1) * 32;
            #pragma unroll
            for (int i = 0; i < 8; i++) {
                const int row = lt + (i >> 2) * 64, c = i & 3;
                v[i] = *reinterpret_cast<const uint4*>(
                    src + (size_t)(row0 + row) * ld + k0 + c * 8);
            }
        }

        const uint32_t sAh = sbase + buf * BUF_B;
        const uint32_t sAl = sAh + TILE_B;
        const uint32_t sBh = sAh + 2 * TILE_B;
        const uint32_t sBl = sAh + 3 * TILE_B;

        #pragma unroll
        for (int ks = 0; ks < 2; ks++) {
            uint32_t ahi[4][4], alo[4][4], bhi[4][2], blo[4][2];
            #pragma unroll
            for (int mt = 0; mt < 4; mt++) {
                const uint32_t off = (uint32_t)(wr * 64 + mt * 16 + a_r) * ROWB
                                   + (uint32_t)(ks * 2 + a_c) * 16;
                ldm_x4(ahi[mt], sAh + off);
                ldm_x4(alo[mt], sAl + off);
            }
            #pragma unroll
            for (int p = 0; p < 2; p++) {
                const uint32_t off = (uint32_t)(wc * 32 + p * 16 + b_r) * ROWB
                                   + (uint32_t)(ks * 2 + b_c) * 16;
                uint32_t th[4], tl[4];
                ldm_x4(th, sBh + off);
                ldm_x4(tl, sBl + off);
                bhi[2 * p][0] = th[0]; bhi[2 * p][1] = th[1];
                bhi[2 * p + 1][0] = th[2]; bhi[2 * p + 1][1] = th[3];
                blo[2 * p][0] = tl[0]; blo[2 * p][1] = tl[1];
                blo[2 * p + 1][0] = tl[2]; blo[2 * p + 1][1] = tl[3];
            }
            #pragma unroll
            for (int mt = 0; mt < 4; mt++)
                #pragma unroll
                for (int nt = 0; nt < 4; nt++) {
                    mma_bf16(acc[mt][nt], ahi[mt], bhi[nt][0], bhi[nt][1]);
                    mma_bf16(acc[mt][nt], ahi[mt], blo[nt][0], blo[nt][1]);
                    mma_bf16(acc[mt][nt], alo[mt], bhi[nt][0], bhi[nt][1]);
                }
        }

        if (t + 1 < NT) {
            char* sb = smem + (buf ^ 1) * BUF_B + oh * TILE_B;
            #pragma unroll
            for (int i = 0; i < 8; i++) {
                const int row = lt + (i >> 2) * 64, c = i & 3;
                *reinterpret_cast<uint4*>(sb + row * ROWB + c * 16) = v[i];
            }
        }
        buf ^= 1;
    }

    // epilogue: fragment layout lane -> (row = lane>>2 [+8], cols (lane&3)*2, +1)
    #pragma unroll
    for (int mt = 0; mt < 4; mt++)
        #pragma unroll
        for (int nt = 0; nt < 4; nt++) {
            const int row = m0 + wr * 64 + mt * 16 + (lane >> 2);
            const int col = n0 + wc * 32 + nt * 8 + (lane & 3) * 2;
            const float* d = acc[mt][nt];

            if (MODE == 0 || MODE == 1) {
                float q0, q1, q2, q3;
                if (MODE == 0) {
                    const float c0 = g_bias[col], c1 = g_bias[col + 1];
                    q0 = d[0] + c0; q1 = d[1] + c1; q2 = d[2] + c0; q3 = d[3] + c1;
                } else {
                    q0 = d[0] + g_bias[1024 + row];
                    q1 = d[1] + g_bias[1024 + row];
                    q2 = d[2] + g_bias[1024 + row + 8];
                    q3 = d[3] + g_bias[1024 + row + 8];
                }
                __nv_bfloat16 h0, l0, h1, l1, h2, l2, h3, l3;
                split_bf16(q0, h0, l0); split_bf16(q1, h1, l1);
                split_bf16(q2, h2, l2); split_bf16(q3, h3, l3);
                const int rows = (MODE == 0) ? Nd : Cd;  (void)rows;
                const size_t o0 = ((size_t)bz * ((MODE == 0) ? Nd : Cd) + row) * Nd + col;
                const size_t o1 = o0 + 8 * Nd;
                __nv_bfloat16* dh = (MODE == 0) ? g_featT_hi : g_beta_hi;
                __nv_bfloat16* dl = (MODE == 0) ? g_featT_lo : g_beta_lo;
                *reinterpret_cast<uint32_t*>(dh + o0) =
                    (uint32_t)__bfloat16_as_ushort(h0) | ((uint32_t)__bfloat16_as_ushort(h1) << 16);
                *reinterpret_cast<uint32_t*>(dl + o0) =
                    (uint32_t)__bfloat16_as_ushort(l0) | ((uint32_t)__bfloat16_as_ushort(l1) << 16);
                *reinterpret_cast<uint32_t*>(dh + o1) =
                    (uint32_t)__bfloat16_as_ushort(h2) | ((uint32_t)__bfloat16_as_ushort(h3) << 16);
                *reinterpret_cast<uint32_t*>(dl + o1) =
                    (uint32_t)__bfloat16_as_ushort(l2) | ((uint32_t)__bfloat16_as_ushort(l3) << 16);
            } else if (MODE == 2) {
                const size_t o0 = ((size_t)bz * Nd + row) * Nd + col;
                *reinterpret_cast<float2*>(g_S + o0) = make_float2(d[0], d[1]);
                *reinterpret_cast<float2*>(g_S + o0 + 8 * Nd) = make_float2(d[2], d[3]);
            } else {
                const size_t o0 = ((size_t)bz * Cd + row) * Nd + col;
                const size_t o1 = o0 + 8 * Nd;
                float2 x0 = *reinterpret_cast<const float2*>(Xres + o0);
                float2 x1 = *reinterpret_cast<const float2*>(Xres + o1);
                *reinterpret_cast<float2*>(Out + o0) = make_float2(d[0] + x0.x, d[1] + x0.y);
                *reinterpret_cast<float2*>(Out + o1) = make_float2(d[2] + x1.x, d[3] + x1.y);
            }
        }
}

// ---------------------------------------------------------------------------
extern "C" void kernel_launch(void* const* d_in, const int* in_sizes, int n_in,
                              void* d_out, int out_size)
{
    (void)in_sizes; (void)n_in; (void)out_size;
    const float* X  = (const float*)d_in[0];
    const float* Wp = (const float*)d_in[1];
    const float* bp = (const float*)d_in[2];
    const float* Wt = (const float*)d_in[3];
    const float* bt = (const float*)d_in[4];
    const float* Wb = (const float*)d_in[5];
    const float* bb = (const float*)d_in[6];
    float* out = (float*)d_out;

    static bool attr_done = false;
    if (!attr_done) {
        cudaFuncSetAttribute(k_gemm<0>, cudaFuncAttributeMaxDynamicSharedMemorySize, SM_TOTAL);
        cudaFuncSetAttribute(k_gemm<1>, cudaFuncAttributeMaxDynamicSharedMemorySize, SM_TOTAL);
        cudaFuncSetAttribute(k_gemm<2>, cudaFuncAttributeMaxDynamicSharedMemorySize, SM_TOTAL);
        cudaFuncSetAttribute(k_gemm<3>, cudaFuncAttributeMaxDynamicSharedMemorySize, SM_TOTAL);
        attr_done = true;
    }

    k_prep_w <<<(3 * Cd * Cd) / 256, 256>>>(Wp, bp, Wt, bt, Wb, bb);
    k_prep_x <<<dim3(Nd / 32, Cd / 32, Bd), dim3(32, 8)>>>(X);
    k_gemm<0><<<dim3(8, 8, Bd), 256, SM_TOTAL>>>(nullptr, nullptr);  // conv1 -> featT
    k_gemm<1><<<dim3(8, 4, Bd), 256, SM_TOTAL>>>(nullptr, nullptr);  // conv2 -> beta
    k_gemm<2><<<dim3(8, 8, Bd), 256, SM_TOTAL>>>(nullptr, nullptr);  // scores -> S
    k_softmax<<<Bd * Nd, 256>>>();
    k_trS    <<<dim3(Nd / 32, Nd / 32, Bd), dim3(32, 8)>>>();
    k_gemm<3><<<dim3(8, 4, Bd), 256, SM_TOTAL>>>(X, out);            // z -> out
}

// round 7
// speedup vs baseline: 2.4183x; 1.4600x over previous
#include <cuda_runtime.h>
#include <cuda_bf16.h>
#include <cstdint>

// ---------------------------------------------------------------------------
// Non-local attention block, B=8, C=512, N=1024 (H=W=32), fp32 in/out.
// R6: mma.sync bf16 x3-pass split GEMMs + cp.async 2-stage pipeline,
//     2 CTAs/SM (launch_bounds(256,2)), reduced register footprint.
// ---------------------------------------------------------------------------

namespace {
constexpr int Cd = 512, Nd = 1024, Bd = 8;
constexpr int ROWB   = 80;                 // padded smem row (32 bf16 = 64B data)
constexpr int TILE_B = 128 * ROWB;         // 10240 B per operand-half tile
constexpr int BUF_B  = 4 * TILE_B;         // Ahi,Alo,Bhi,Blo = 40960
constexpr int SM_TOTAL = 2 * BUF_B;        // 81920 (double buffer)
}

// ---- device scratch --------------------------------------------------------
__device__ __nv_bfloat16 g_XT_hi[Bd * Nd * Cd];
__device__ __nv_bfloat16 g_XT_lo[Bd * Nd * Cd];
__device__ __nv_bfloat16 g_Wsp_hi[3 * Cd * Cd];   // phi 0-511, theta 512-1023, beta 1024-1535
__device__ __nv_bfloat16 g_Wsp_lo[3 * Cd * Cd];
__device__ float         g_bias[3 * Cd];
__device__ __nv_bfloat16 g_featT_hi[Bd * Nd * Nd]; // [b][n][r], r: phi 0-511, theta 512-1023
__device__ __nv_bfloat16 g_featT_lo[Bd * Nd * Nd];
__device__ __nv_bfloat16 g_beta_hi[Bd * Cd * Nd];  // [b][c][n]
__device__ __nv_bfloat16 g_beta_lo[Bd * Cd * Nd];
__device__ float         g_S[Bd * Nd * Nd];        // [b][n][m]
__device__ __nv_bfloat16 g_AT_hi[Bd * Nd * Nd];    // [b][m][n]
__device__ __nv_bfloat16 g_AT_lo[Bd * Nd * Nd];

// ---- helpers ---------------------------------------------------------------
__device__ __forceinline__ uint32_t smem_u32(const void* p) {
    uint32_t a;
    asm("{ .reg .u64 t; cvta.to.shared.u64 t, %1; cvt.u32.u64 %0, t; }"
        : "=r"(a) : "l"(p));
    return a;
}
__device__ __forceinline__ void cp16(uint32_t dst, const void* src) {
    asm volatile("cp.async.cg.shared.global [%0], [%1], 16;"
                 :: "r"(dst), "l"(__cvta_generic_to_global(src)) : "memory");
}
__device__ __forceinline__ void cp_commit() {
    asm volatile("cp.async.commit_group;" ::: "memory");
}
__device__ __forceinline__ void cp_wait1() {
    asm volatile("cp.async.wait_group 1;" ::: "memory");
}
__device__ __forceinline__ void cp_wait0() {
    asm volatile("cp.async.wait_group 0;" ::: "memory");
}
__device__ __forceinline__ void ldm_x4(uint32_t (&r)[4], uint32_t addr) {
    asm volatile("ldmatrix.sync.aligned.m8n8.x4.shared.b16 {%0,%1,%2,%3}, [%4];"
        : "=r"(r[0]), "=r"(r[1]), "=r"(r[2]), "=r"(r[3]) : "r"(addr));
}
__device__ __forceinline__ void mma_bf16(float (&d)[4], const uint32_t (&a)[4],
                                         const uint32_t b0, const uint32_t b1) {
    asm volatile(
        "mma.sync.aligned.m16n8k16.row.col.f32.bf16.bf16.f32 "
        "{%0,%1,%2,%3},{%4,%5,%6,%7},{%8,%9},{%0,%1,%2,%3};"
        : "+f"(d[0]), "+f"(d[1]), "+f"(d[2]), "+f"(d[3])
        : "r"(a[0]), "r"(a[1]), "r"(a[2]), "r"(a[3]), "r"(b0), "r"(b1));
}
__device__ __forceinline__ void split_bf16(float v, __nv_bfloat16& h, __nv_bfloat16& l) {
    h = __float2bfloat16(v);
    l = __float2bfloat16(v - __bfloat162float(h));
}

// ---------------------------------------------------------------------------
// prep W: split the three weight matrices into stacked bf16 hi/lo + bias
// ---------------------------------------------------------------------------
__global__ __launch_bounds__(256)
void k_prep_w(const float* __restrict__ Wp, const float* __restrict__ bp,
              const float* __restrict__ Wt, const float* __restrict__ bt,
              const float* __restrict__ Wb, const float* __restrict__ bb)
{
    int i = blockIdx.x * 256 + threadIdx.x;   // < 1536*512
    int r = i >> 9, c = i & 511;
    const float* W = (r < 512) ? Wp : (r < 1024) ? Wt : Wb;
    float v = W[(size_t)(r & 511) * Cd + c];
    split_bf16(v, g_Wsp_hi[i], g_Wsp_lo[i]);
    if (i < 3 * Cd)
        g_bias[i] = (i < 512) ? bp[i] : (i < 1024) ? bt[i - 512] : bb[i - 1024];
}

// ---------------------------------------------------------------------------
// prep X: transpose + split: XT[b][n][c] = X[b][c][n]
// ---------------------------------------------------------------------------
__global__ __launch_bounds__(256)
void k_prep_x(const float* __restrict__ X)
{
    __shared__ float t[32][33];
    const int b = blockIdx.z, n0 = blockIdx.x * 32, c0 = blockIdx.y * 32;
    const int tx = threadIdx.x, ty = threadIdx.y;
    #pragma unroll
    for (int r = 0; r < 4; r++)
        t[ty + 8 * r][tx] = X[((size_t)b * Cd + c0 + ty + 8 * r) * Nd + n0 + tx];
    __syncthreads();
    #pragma unroll
    for (int r = 0; r < 4; r++) {
        float v = t[tx][ty + 8 * r];
        size_t o = ((size_t)b * Nd + n0 + ty + 8 * r) * Cd + c0 + tx;
        split_bf16(v, g_XT_hi[o], g_XT_lo[o]);
    }
}

// ---------------------------------------------------------------------------
// transpose + split post-softmax attention: AT[b][m][n] = S[b][n][m]
// ---------------------------------------------------------------------------
__global__ __launch_bounds__(256)
void k_trS()
{
    __shared__ float t[32][33];
    const int b = blockIdx.z, m0 = blockIdx.x * 32, n0 = blockIdx.y * 32;
    const int tx = threadIdx.x, ty = threadIdx.y;
    #pragma unroll
    for (int r = 0; r < 4; r++)
        t[ty + 8 * r][tx] = g_S[((size_t)b * Nd + n0 + ty + 8 * r) * Nd + m0 + tx];
    __syncthreads();
    #pragma unroll
    for (int r = 0; r < 4; r++) {
        float v = t[tx][ty + 8 * r];
        size_t o = ((size_t)b * Nd + m0 + ty + 8 * r) * Nd + n0 + tx;
        split_bf16(v, g_AT_hi[o], g_AT_lo[o]);
    }
}

// ---------------------------------------------------------------------------
// row softmax of g_S (8192 rows x 1024), fp32 in place
// ---------------------------------------------------------------------------
__global__ __launch_bounds__(256)
void k_softmax()
{
    __shared__ float red[8];
    float* __restrict__ p = g_S + (size_t)blockIdx.x * Nd;
    const int tid = threadIdx.x, lane = tid & 31, warp = tid >> 5;

    float4 v = *reinterpret_cast<const float4*>(p + tid * 4);
    float m = fmaxf(fmaxf(v.x, v.y), fmaxf(v.z, v.w));
    #pragma unroll
    for (int o = 16; o; o >>= 1) m = fmaxf(m, __shfl_xor_sync(0xffffffffu, m, o));
    if (lane == 0) red[warp] = m;
    __syncthreads();
    float rowmax = red[0];
    #pragma unroll
    for (int i = 1; i < 8; i++) rowmax = fmaxf(rowmax, red[i]);
    __syncthreads();

    float4 e;
    e.x = __expf(v.x - rowmax); e.y = __expf(v.y - rowmax);
    e.z = __expf(v.z - rowmax); e.w = __expf(v.w - rowmax);
    float s = (e.x + e.y) + (e.z + e.w);
    #pragma unroll
    for (int o = 16; o; o >>= 1) s += __shfl_xor_sync(0xffffffffu, s, o);
    if (lane == 0) red[warp] = s;
    __syncthreads();
    float rowsum = red[0];
    #pragma unroll
    for (int i = 1; i < 8; i++) rowsum += red[i];

    const float inv = 1.0f / rowsum;
    e.x *= inv; e.y *= inv; e.z *= inv; e.w *= inv;
    *reinterpret_cast<float4*>(p + tid * 4) = e;
}

// ---------------------------------------------------------------------------
// mma.sync GEMM, cp.async double-buffered, 2 CTAs/SM.
// D[128x128] fp32 = 3-pass (hh, hl, lh) over bf16 split operands, K-major both.
// MODE 0: conv1  D[n][r] = XT . Wsp(0:1024)   K=512  -> featT split (+bias[col])
// MODE 1: conv2  D[c][n] = Wsp(beta) . XT     K=512  -> beta  split (+bias[row])
// MODE 2: scores D[n][m] = phiT . thetaT      K=512  -> g_S fp32
// MODE 3: z      D[c][m] = beta . AT  (+X)    K=1024 -> out fp32
// ---------------------------------------------------------------------------
template <int MODE>
__global__ __launch_bounds__(256, 2)
void k_gemm(const float* __restrict__ Xres, float* __restrict__ Out)
{
    extern __shared__ __align__(128) char smem[];
    const uint32_t sbase = smem_u32(smem);
    const int tid = threadIdx.x;
    const int lane = tid & 31, wid = tid >> 5;
    const int wr = wid >> 2, wc = wid & 3;          // 2x4 warp grid
    const int bz = blockIdx.z;
    const int m0 = blockIdx.y * 128, n0 = blockIdx.x * 128;

    const __nv_bfloat16 *Ah, *Al, *Bh, *Bl;
    int ldA, ldB;
    constexpr int K = (MODE == 3) ? Nd : Cd;
    if (MODE == 0) {
        Ah = g_XT_hi + (size_t)bz * Nd * Cd;  Al = g_XT_lo + (size_t)bz * Nd * Cd;
        Bh = g_Wsp_hi;                        Bl = g_Wsp_lo;
        ldA = Cd; ldB = Cd;
    } else if (MODE == 1) {
        Ah = g_Wsp_hi + (size_t)1024 * Cd;    Al = g_Wsp_lo + (size_t)1024 * Cd;
        Bh = g_XT_hi + (size_t)bz * Nd * Cd;  Bl = g_XT_lo + (size_t)bz * Nd * Cd;
        ldA = Cd; ldB = Cd;
    } else if (MODE == 2) {
        Ah = g_featT_hi + (size_t)bz * Nd * Nd;        Al = g_featT_lo + (size_t)bz * Nd * Nd;
        Bh = g_featT_hi + (size_t)bz * Nd * Nd + 512;  Bl = g_featT_lo + (size_t)bz * Nd * Nd + 512;
        ldA = Nd; ldB = Nd;
    } else {
        Ah = g_beta_hi + (size_t)bz * Cd * Nd;  Al = g_beta_lo + (size_t)bz * Cd * Nd;
        Bh = g_AT_hi + (size_t)bz * Nd * Nd;    Bl = g_AT_lo + (size_t)bz * Nd * Nd;
        ldA = Nd; ldB = Nd;
    }

    // loader role: quarter oh -> one operand-half; 8 cp.async per k-tile
    const int oh = tid >> 6, lt = tid & 63;
    const __nv_bfloat16* src;
    int row0, ld;
    if      (oh == 0) { src = Ah; row0 = m0; ld = ldA; }
    else if (oh == 1) { src = Al; row0 = m0; ld = ldA; }
    else if (oh == 2) { src = Bh; row0 = n0; ld = ldB; }
    else              { src = Bl; row0 = n0; ld = ldB; }

    auto cp_tile = [&](int buf, int k0) {
        const uint32_t sb = sbase + buf * BUF_B + oh * TILE_B;
        #pragma unroll
        for (int i = 0; i < 8; i++) {
            const int j = i * 64 + lt;
            const int row = j >> 2, c = j & 3;
            cp16(sb + row * ROWB + c * 16,
                 src + (size_t)(row0 + row) * ld + k0 + c * 8);
        }
        cp_commit();
    };

    float acc[4][4][4];
    #pragma unroll
    for (int i = 0; i < 4; i++)
        #pragma unroll
        for (int j = 0; j < 4; j++)
            #pragma unroll
            for (int q = 0; q < 4; q++) acc[i][j][q] = 0.f;

    // ldmatrix lane address components
    const int a_r = lane & 15, a_c = lane >> 4;              // A: rows 0-15, chunk half
    const int b_r = (lane & 7) + ((lane & 16) >> 1);         // B: n within 16
    const int b_c = (lane >> 3) & 1;                         // B: chunk half

    cp_tile(0, 0);

    constexpr int NT = K / 32;
    int buf = 0;
    for (int t = 0; t < NT; t++) {
        if (t + 1 < NT) { cp_tile(buf ^ 1, (t + 1) * 32); cp_wait1(); }
        else            { cp_wait0(); }
        __syncthreads();

        const uint32_t sAh = sbase + buf * BUF_B;
        const uint32_t sAl = sAh + TILE_B;
        const uint32_t sBh = sAh + 2 * TILE_B;
        const uint32_t sBl = sAh + 3 * TILE_B;

        #pragma unroll
        for (int ks = 0; ks < 2; ks++) {
            uint32_t bhi[4][2], blo[4][2];
            #pragma unroll
            for (int p = 0; p < 2; p++) {
                const uint32_t off = (uint32_t)(wc * 32 + p * 16 + b_r) * ROWB
                                   + (uint32_t)(ks * 2 + b_c) * 16;
                uint32_t th[4], tl[4];
                ldm_x4(th, sBh + off);
                ldm_x4(tl, sBl + off);
                bhi[2 * p][0] = th[0]; bhi[2 * p][1] = th[1];
                bhi[2 * p + 1][0] = th[2]; bhi[2 * p + 1][1] = th[3];
                blo[2 * p][0] = tl[0]; blo[2 * p][1] = tl[1];
                blo[2 * p + 1][0] = tl[2]; blo[2 * p + 1][1] = tl[3];
            }
            #pragma unroll
            for (int mt = 0; mt < 4; mt++) {
                uint32_t ahi[4], alo[4];
                const uint32_t off = (uint32_t)(wr * 64 + mt * 16 + a_r) * ROWB
                                   + (uint32_t)(ks * 2 + a_c) * 16;
                ldm_x4(ahi, sAh + off);
                ldm_x4(alo, sAl + off);
                #pragma unroll
                for (int nt = 0; nt < 4; nt++) {
                    mma_bf16(acc[mt][nt], ahi, bhi[nt][0], bhi[nt][1]);
                    mma_bf16(acc[mt][nt], ahi, blo[nt][0], blo[nt][1]);
                    mma_bf16(acc[mt][nt], alo, bhi[nt][0], bhi[nt][1]);
                }
            }
        }
        __syncthreads();   // protect buf^1 (written by cp.async next iteration)
        buf ^= 1;
    }

    // epilogue: fragment lane -> (row = lane>>2 [+8], cols (lane&3)*2, +1)
    #pragma unroll
    for (int mt = 0; mt < 4; mt++)
        #pragma unroll
        for (int nt = 0; nt < 4; nt++) {
            const int row = m0 + wr * 64 + mt * 16 + (lane >> 2);
            const int col = n0 + wc * 32 + nt * 8 + (lane & 3) * 2;
            const float* d = acc[mt][nt];

            if (MODE == 0 || MODE == 1) {
                float q0, q1, q2, q3;
                if (MODE == 0) {
                    const float c0 = g_bias[col], c1 = g_bias[col + 1];
                    q0 = d[0] + c0; q1 = d[1] + c1; q2 = d[2] + c0; q3 = d[3] + c1;
                } else {
                    q0 = d[0] + g_bias[1024 + row];
                    q1 = d[1] + g_bias[1024 + row];
                    q2 = d[2] + g_bias[1024 + row + 8];
                    q3 = d[3] + g_bias[1024 + row + 8];
                }
                __nv_bfloat16 h0, l0, h1, l1, h2, l2, h3, l3;
                split_bf16(q0, h0, l0); split_bf16(q1, h1, l1);
                split_bf16(q2, h2, l2); split_bf16(q3, h3, l3);
                const size_t o0 = ((size_t)bz * ((MODE == 0) ? Nd : Cd) + row) * Nd + col;
                const size_t o1 = o0 + 8 * Nd;
                __nv_bfloat16* dh = (MODE == 0) ? g_featT_hi : g_beta_hi;
                __nv_bfloat16* dl = (MODE == 0) ? g_featT_lo : g_beta_lo;
                *reinterpret_cast<uint32_t*>(dh + o0) =
                    (uint32_t)__bfloat16_as_ushort(h0) | ((uint32_t)__bfloat16_as_ushort(h1) << 16);
                *reinterpret_cast<uint32_t*>(dl + o0) =
                    (uint32_t)__bfloat16_as_ushort(l0) | ((uint32_t)__bfloat16_as_ushort(l1) << 16);
                *reinterpret_cast<uint32_t*>(dh + o1) =
                    (uint32_t)__bfloat16_as_ushort(h2) | ((uint32_t)__bfloat16_as_ushort(h3) << 16);
                *reinterpret_cast<uint32_t*>(dl + o1) =
                    (uint32_t)__bfloat16_as_ushort(l2) | ((uint32_t)__bfloat16_as_ushort(l3) << 16);
            } else if (MODE == 2) {
                const size_t o0 = ((size_t)bz * Nd + row) * Nd + col;
                *reinterpret_cast<float2*>(g_S + o0) = make_float2(d[0], d[1]);
                *reinterpret_cast<float2*>(g_S + o0 + 8 * Nd) = make_float2(d[2], d[3]);
            } else {
                const size_t o0 = ((size_t)bz * Cd + row) * Nd + col;
                const size_t o1 = o0 + 8 * Nd;
                float2 x0 = *reinterpret_cast<const float2*>(Xres + o0);
                float2 x1 = *reinterpret_cast<const float2*>(Xres + o1);
                *reinterpret_cast<float2*>(Out + o0) = make_float2(d[0] + x0.x, d[1] + x0.y);
                *reinterpret_cast<float2*>(Out + o1) = make_float2(d[2] + x1.x, d[3] + x1.y);
            }
        }
}

// ---------------------------------------------------------------------------
extern "C" void kernel_launch(void* const* d_in, const int* in_sizes, int n_in,
                              void* d_out, int out_size)
{
    (void)in_sizes; (void)n_in; (void)out_size;
    const float* X  = (const float*)d_in[0];
    const float* Wp = (const float*)d_in[1];
    const float* bp = (const float*)d_in[2];
    const float* Wt = (const float*)d_in[3];
    const float* bt = (const float*)d_in[4];
    const float* Wb = (const float*)d_in[5];
    const float* bb = (const float*)d_in[6];
    float* out = (float*)d_out;

    static bool attr_done = false;
    if (!attr_done) {
        cudaFuncSetAttribute(k_gemm<0>, cudaFuncAttributeMaxDynamicSharedMemorySize, SM_TOTAL);
        cudaFuncSetAttribute(k_gemm<1>, cudaFuncAttributeMaxDynamicSharedMemorySize, SM_TOTAL);
        cudaFuncSetAttribute(k_gemm<2>, cudaFuncAttributeMaxDynamicSharedMemorySize, SM_TOTAL);
        cudaFuncSetAttribute(k_gemm<3>, cudaFuncAttributeMaxDynamicSharedMemorySize, SM_TOTAL);
        attr_done = true;
    }

    k_prep_w <<<(3 * Cd * Cd) / 256, 256>>>(Wp, bp, Wt, bt, Wb, bb);
    k_prep_x <<<dim3(Nd / 32, Cd / 32, Bd), dim3(32, 8)>>>(X);
    k_gemm<0><<<dim3(8, 8, Bd), 256, SM_TOTAL>>>(nullptr, nullptr);  // conv1 -> featT
    k_gemm<1><<<dim3(8, 4, Bd), 256, SM_TOTAL>>>(nullptr, nullptr);  // conv2 -> beta
    k_gemm<2><<<dim3(8, 8, Bd), 256, SM_TOTAL>>>(nullptr, nullptr);  // scores -> S
    k_softmax<<<Bd * Nd, 256>>>();
    k_trS    <<<dim3(Nd / 32, Nd / 32, Bd), dim3(32, 8)>>>();
    k_gemm<3><<<dim3(8, 4, Bd), 256, SM_TOTAL>>>(X, out);            // z -> out
}